// round 15
// baseline (speedup 1.0000x reference)
#include <cuda_runtime.h>
#include <cstdint>

#define NN   4096
#define BB   8
#define FIN  40
#define HH   64
#define KK   5
#define LL   4092   // N - K + 1

#define RC1  128    // colsum row chunks (32 rows each)
#define NS   128    // kB row strips (32 rows each)
#define NBB  512    // kB block count (4 col-blocks x 128 strips)

// ---- scratch (static device memory; every element rewritten each launch) ----
__device__ float d_Tpart[RC1][NN];          // partial column sums of A
__device__ float d_sgpart[NS][KK];          // per-strip partial sums of g
__device__ float d_xtT[KK][BB * NN];        // X~T[k][b][m]  (m contiguous)
__device__ float d_ypartB[NBB][BB];         // per-kB-block y partials
__device__ float d_tk[KK];                  // t[k] = b1 . r[k]
__device__ float d_misc[2];                 // bias2, C0
__device__ unsigned int d_done;             // ticket counter (reset by epilogue block)

// ---- cp.async helpers ----
__device__ __forceinline__ void cp_async16(void* smem_ptr, const void* gptr) {
    uint32_t saddr = (uint32_t)__cvta_generic_to_shared(smem_ptr);
    asm volatile("cp.async.cg.shared.global [%0], [%1], 16;" :: "r"(saddr), "l"(gptr));
}
__device__ __forceinline__ void cp_commit() {
    asm volatile("cp.async.commit_group;");
}

// ---- weight fold (redundant per block that needs it) ----
__device__ __forceinline__ void fold_weights(
    const float* __restrict__ W2, const float* __restrict__ cw,
    const float* __restrict__ fw,
    float (&q_s)[HH][KK], float (&r_s)[KK][HH], int t)
{
    for (int idx = t; idx < HH * KK; idx += 256) {
        int i = idx / KK, k = idx % KK;
        float s = 0.f;
        for (int o = 0; o < HH; o++) s += __ldg(&fw[o]) * __ldg(&cw[(o * HH + i) * KK + k]);
        q_s[i][k] = s;
    }
    __syncthreads();
    for (int idx = t; idx < KK * HH; idx += 256) {
        int k = idx / HH, h = idx % HH;
        float s = 0.f;
        for (int i = 0; i < HH; i++) s += __ldg(&W2[h * HH + i]) * q_s[i][k];
        r_s[k][h] = s;
    }
    __syncthreads();
}

// ============================================================
// Kernel A: 577 blocks x 256 threads (unchanged from R13/R14 passing version).
//   blocks [0,512): partial column sums of A (32 rows each)
//   blocks [512,576): X~T[k][b][m] = sum_f x[b][m][f] * s[k][f]
//   block 576: t_k, bias2, C0
// ============================================================
__global__ void __launch_bounds__(256) kA(
    const float* __restrict__ A, const float* __restrict__ x,
    const float* __restrict__ W1, const float* __restrict__ b1,
    const float* __restrict__ W2, const float* __restrict__ b2,
    const float* __restrict__ cw, const float* __restrict__ cb,
    const float* __restrict__ fw, const float* __restrict__ fb)
{
    const int bid = blockIdx.x;
    const int t   = threadIdx.x;

    if (bid < 512) {
        const int c4 = (bid & 3) * 256 + t;          // float4 col index
        const int n0 = (bid >> 2) * 32;
        const float4* Ap = reinterpret_cast<const float4*>(A);
        float4 acc = make_float4(0.f, 0.f, 0.f, 0.f);
#pragma unroll 8
        for (int n = n0; n < n0 + 32; n++) {
            float4 a = __ldg(&Ap[n * (NN / 4) + c4]);
            acc.x += a.x; acc.y += a.y; acc.z += a.z; acc.w += a.w;
        }
        *reinterpret_cast<float4*>(&d_Tpart[bid >> 2][c4 * 4]) = acc;
        return;
    }

    __shared__ float q_s[HH][KK];
    __shared__ float r_s[KK][HH];
    fold_weights(W2, cw, fw, q_s, r_s, t);

    if (bid < 576) {
        __shared__ float s_s[KK][FIN];
        for (int idx = t; idx < KK * FIN; idx += 256) {
            int k = idx / FIN, f = idx % FIN;
            float s = 0.f;
            for (int h = 0; h < HH; h++) s += __ldg(&W1[f * HH + h]) * r_s[k][h];
            s_s[k][f] = s;
        }
        __syncthreads();

        const int bid2 = bid - 512;                  // 0..63
#pragma unroll
        for (int j = 0; j < 2; j++) {
            const int gr = bid2 * 512 + j * 256 + t; // global (b,m) row, 0..32767
            const float4* xp = reinterpret_cast<const float4*>(x) + (size_t)gr * (FIN / 4);
            float d0 = 0.f, d1 = 0.f, d2 = 0.f, d3 = 0.f, d4 = 0.f;
#pragma unroll
            for (int f4 = 0; f4 < FIN / 4; f4++) {
                float4 xv = __ldg(&xp[f4]);
                d0 += xv.x * s_s[0][f4*4] + xv.y * s_s[0][f4*4+1] + xv.z * s_s[0][f4*4+2] + xv.w * s_s[0][f4*4+3];
                d1 += xv.x * s_s[1][f4*4] + xv.y * s_s[1][f4*4+1] + xv.z * s_s[1][f4*4+2] + xv.w * s_s[1][f4*4+3];
                d2 += xv.x * s_s[2][f4*4] + xv.y * s_s[2][f4*4+1] + xv.z * s_s[2][f4*4+2] + xv.w * s_s[2][f4*4+3];
                d3 += xv.x * s_s[3][f4*4] + xv.y * s_s[3][f4*4+1] + xv.z * s_s[3][f4*4+2] + xv.w * s_s[3][f4*4+3];
                d4 += xv.x * s_s[4][f4*4] + xv.y * s_s[4][f4*4+1] + xv.z * s_s[4][f4*4+2] + xv.w * s_s[4][f4*4+3];
            }
            // transposed, coalesced across t (gr consecutive)
            d_xtT[0][gr] = d0;
            d_xtT[1][gr] = d1;
            d_xtT[2][gr] = d2;
            d_xtT[3][gr] = d3;
            d_xtT[4][gr] = d4;
        }
        return;
    }

    if (t < KK) {
        float s = 0.f;
        for (int h = 0; h < HH; h++) s += __ldg(&b1[h]) * r_s[t][h];
        d_tk[t] = s;
    }
    if (t == 0) {
        float bias2 = 0.f;
        for (int i = 0; i < HH; i++)
            for (int k = 0; k < KK; k++) bias2 += q_s[i][k] * __ldg(&b2[i]);
        float C0 = __ldg(&fb[0]);
        for (int o = 0; o < HH; o++) C0 += __ldg(&fw[o]) * __ldg(&cb[o]);
        d_misc[0] = bias2;
        d_misc[1] = C0;
    }
}

// ============================================================
// Kernel B: grid (4, 128) = 512 blocks x 256 threads; 32-row strips.
// A strip streamed via cp.async double-buffered smem (self-staged per
// thread: no cross-thread sharing -> no syncthreads in the pipeline).
// ============================================================
#define CHR 4    // rows per chunk
#define NCH 8    // chunks per strip (NCH*CHR = 32)

__global__ void __launch_bounds__(256, 4) kB(const float* __restrict__ A,
                                             float* __restrict__ out) {
    __shared__ float4 abuf[2][CHR][256];     // 32 KB double buffer
    __shared__ float gsk[KK][32];
    __shared__ float tred[8][32];
    __shared__ float ywred[8][BB];
    __shared__ bool  is_last;

    const int t   = threadIdx.x;
    const int cb  = blockIdx.x;                  // 0..3
    const int c4  = cb * 256 + t;                // float4 col index
    const int st  = blockIdx.y;                  // strip 0..127
    const int n0  = st * 32;
    const int bi  = st * 4 + cb;                 // 0..511

    const float4* Ap = reinterpret_cast<const float4*>(A);

    // kick off chunk 0 of the A pipeline immediately (overlaps g compute)
#pragma unroll
    for (int r = 0; r < CHR; r++)
        cp_async16(&abuf[0][r][t], &Ap[(n0 + r) * (NN / 4) + c4]);
    cp_commit();

    // --- cooperative Tpart combine: 8 r-groups x 32 rows, 16 partials each ---
    {
        const int nl = t & 31;
        const int rg = t >> 5;                   // 0..7
        float T = 0.f;
#pragma unroll
        for (int r = rg * 16; r < rg * 16 + 16; r++) T += __ldg(&d_Tpart[r][n0 + nl]);
        tred[rg][nl] = T;
    }
    __syncthreads();

    if (t < 32) {
        const int n = n0 + t;
        float T = 0.f;
#pragma unroll
        for (int rg = 0; rg < 8; rg++) T += tred[rg][t];

        float top[4], bot[4];
#pragma unroll
        for (int j = 0; j < 4; j++) top[j] = __ldg(&A[j * NN + n]);
#pragma unroll
        for (int j = 0; j < 4; j++) bot[j] = __ldg(&A[(4092 + j) * NN + n]);
        float cumtop = 0.f;
#pragma unroll
        for (int k = 0; k < KK; k++) {
            float sb = 0.f;
#pragma unroll
            for (int j = 0; j < 4; j++) if (j >= k) sb += bot[j];
            float g = T - cumtop - sb;
            gsk[k][t] = g;
            if (k < 4) cumtop += top[k];
        }
        // per-strip sg partials (col-block 0 only)
        if (cb == 0) {
#pragma unroll
            for (int k = 0; k < KK; k++) {
                float v = gsk[k][t];
#pragma unroll
                for (int ofs = 16; ofs > 0; ofs >>= 1)
                    v += __shfl_down_sync(0xffffffffu, v, ofs);
                if (t == 0) d_sgpart[st][k] = v;
            }
        }
    }
    __syncthreads();

    // --- A-strip accumulation via cp.async pipeline ---
    float acc[KK][4];
#pragma unroll
    for (int k = 0; k < KK; k++)
#pragma unroll
        for (int j = 0; j < 4; j++) acc[k][j] = 0.f;

#pragma unroll
    for (int ch = 0; ch < NCH; ch++) {
        if (ch < NCH - 1) {
            const int rbase = (ch + 1) * CHR;
#pragma unroll
            for (int r = 0; r < CHR; r++)
                cp_async16(&abuf[(ch + 1) & 1][r][t], &Ap[(n0 + rbase + r) * (NN / 4) + c4]);
            cp_commit();
            asm volatile("cp.async.wait_group 1;");
        } else {
            asm volatile("cp.async.wait_group 0;");
        }
#pragma unroll
        for (int r = 0; r < CHR; r++) {
            const int nl = ch * CHR + r;
            float4 a = abuf[ch & 1][r][t];       // self-staged: no block sync needed
            float g0 = gsk[0][nl], g1 = gsk[1][nl], g2 = gsk[2][nl];
            float g3 = gsk[3][nl], g4 = gsk[4][nl];
            acc[0][0] += a.x * g0; acc[0][1] += a.y * g0; acc[0][2] += a.z * g0; acc[0][3] += a.w * g0;
            acc[1][0] += a.x * g1; acc[1][1] += a.y * g1; acc[1][2] += a.z * g1; acc[1][3] += a.w * g1;
            acc[2][0] += a.x * g2; acc[2][1] += a.y * g2; acc[2][2] += a.z * g2; acc[2][3] += a.w * g2;
            acc[3][0] += a.x * g3; acc[3][1] += a.y * g3; acc[3][2] += a.z * g3; acc[3][3] += a.w * g3;
            acc[4][0] += a.x * g4; acc[4][1] += a.y * g4; acc[4][2] += a.z * g4; acc[4][3] += a.w * g4;
        }
    }

    // --- dot with X~T: one coalesced float4 per (b,k) covering this thread's 4 m ---
    float y8[BB];
#pragma unroll
    for (int b = 0; b < BB; b++) y8[b] = 0.f;
#pragma unroll
    for (int b = 0; b < BB; b++) {
#pragma unroll
        for (int k = 0; k < KK; k++) {
            const float4 xv = __ldg(reinterpret_cast<const float4*>(&d_xtT[k][b * NN]) + c4);
            y8[b] += acc[k][0] * xv.x + acc[k][1] * xv.y + acc[k][2] * xv.z + acc[k][3] * xv.w;
        }
    }

    // --- block reduction of y8 ---
#pragma unroll
    for (int b = 0; b < BB; b++) {
#pragma unroll
        for (int ofs = 16; ofs > 0; ofs >>= 1)
            y8[b] += __shfl_down_sync(0xffffffffu, y8[b], ofs);
    }
    if ((t & 31) == 0) {
#pragma unroll
        for (int b = 0; b < BB; b++) ywred[t >> 5][b] = y8[b];
    }
    __syncthreads();
    if (t < BB) {
        float v = 0.f;
#pragma unroll
        for (int w = 0; w < 8; w++) v += ywred[w][t];
        d_ypartB[bi][t] = v;
    }

    // --- non-blocking last-block election ---
    __threadfence();
    __syncthreads();
    if (t == 0) {
        unsigned int old = atomicAdd(&d_done, 1u);
        is_last = (old == NBB - 1);
    }
    __syncthreads();
    if (!is_last) return;

    // ================= epilogue (elected block only) =================
    __shared__ float sg_s[KK];
    __shared__ float y_s[BB];
    if (t < KK * 32) {
        const int k    = t >> 5;
        const int lane = t & 31;
        float v = 0.f;
#pragma unroll
        for (int j = 0; j < NS / 32; j++) v += __ldcg(&d_sgpart[lane + 32 * j][k]);
#pragma unroll
        for (int ofs = 16; ofs > 0; ofs >>= 1)
            v += __shfl_down_sync(0xffffffffu, v, ofs);
        if (lane == 0) sg_s[k] = v;
    }
    __syncthreads();
    {
        const int b    = t >> 5;
        const int lane = t & 31;
        float v = 0.f;
#pragma unroll
        for (int j = 0; j < NBB / 32; j++) v += __ldcg(&d_ypartB[lane + 32 * j][b]);
#pragma unroll
        for (int ofs = 16; ofs > 0; ofs >>= 1)
            v += __shfl_down_sync(0xffffffffu, v, ofs);
        if (lane == 0) y_s[b] = v;
    }
    __syncthreads();
    if (t < BB) {
        float gt = 0.f;
#pragma unroll
        for (int k = 0; k < KK; k++) gt += sg_s[k] * __ldcg(&d_tk[k]);
        out[t] = (y_s[t] + gt) * (1.0f / (float)LL) + __ldcg(&d_misc[0]) + __ldcg(&d_misc[1]);
    }
    if (t == 0) d_done = 0;   // reset ticket for next graph replay
}

// ============================================================
extern "C" void kernel_launch(void* const* d_in, const int* in_sizes, int n_in,
                              void* d_out, int out_size) {
    const float* x   = (const float*)d_in[0];
    const float* A   = (const float*)d_in[1];
    const float* W1  = (const float*)d_in[2];
    const float* b1  = (const float*)d_in[3];
    const float* W2  = (const float*)d_in[4];
    const float* b2  = (const float*)d_in[5];
    const float* cw  = (const float*)d_in[6];
    const float* cb  = (const float*)d_in[7];
    const float* fw  = (const float*)d_in[8];
    const float* fb  = (const float*)d_in[9];
    float* out = (float*)d_out;

    kA<<<577, 256>>>(A, x, W1, b1, W2, b2, cw, cb, fw, fb);
    kB<<<dim3(4, NS), 256>>>(A, out);
}